// round 1
// baseline (speedup 1.0000x reference)
#include <cuda_runtime.h>
#include <math.h>

#define B_SZ 2048
#define KIN  64
#define KOUT 64
#define BLK  256
#define KH   129

// Scratch (device globals: allocation-free per the rules)
__device__ float2 g_X[(size_t)B_SZ * KH * KIN];   // [b][f][j]  ~135 MB
__device__ float2 g_Y[(size_t)B_SZ * KH * KOUT];  // [b][f][i]  ~135 MB
__device__ float2 g_W[(size_t)KH * KOUT * KIN];   // [f][i][j]  ~4.2 MB

// ---------------------------------------------------------------------------
// Kernel 1: transpose W (i,j,f) -> (f,i,j) as complex
// ---------------------------------------------------------------------------
__global__ void prep_w(const float* __restrict__ Wr, const float* __restrict__ Wi) {
    int idx = blockIdx.x * blockDim.x + threadIdx.x;
    if (idx >= KH * KOUT * KIN) return;
    int j = idx & 63;
    int i = (idx >> 6) & 63;
    int f = idx >> 12;
    float2 v;
    v.x = Wr[(i * KIN + j) * KH + f];
    v.y = Wi[(i * KIN + j) * KH + f];
    g_W[idx] = v;
}

// ---------------------------------------------------------------------------
// Kernel 2: forward rFFT (256-pt, 16x16 Cooley-Tukey, 16 threads per FFT)
// CTA: one b, 16 j-blocks. Writes X[b][f][j], f = 0..128 only.
// ---------------------------------------------------------------------------
__global__ __launch_bounds__(256) void fft_fwd(const float* __restrict__ x) {
    __shared__ float2 tw[256];           // tw[k] = e^{-2pi i k/256}
    __shared__ float2 sbuf[16 * 16 * 17]; // 4352 float2 (34.8 KB), multi-use

    int tid = threadIdx.x;
    {
        float s, c;
        sincospif(-(float)tid * (1.0f / 128.0f), &s, &c);
        tw[tid] = make_float2(c, s);
    }
    int cta = blockIdx.x;
    int b  = cta >> 2;
    int j0 = (cta & 3) << 4;
    int g  = tid >> 4;   // FFT index within CTA (j = j0+g)
    int t  = tid & 15;   // lane within FFT: n2 in stage 1, f1 in stage 2

    // Load x[16*n1 + t] for this block
    const float* xp = x + (size_t)b * 16384 + (size_t)(j0 + g) * 256 + t;
    float xr[16];
#pragma unroll
    for (int n1 = 0; n1 < 16; n1++) xr[n1] = xp[n1 * 16];

    __syncthreads(); // twiddle table ready

    // Stage 1: A'[n2][f1] = (sum_n1 x[16n1+n2] e^{-2pi i n1 f1/16}) * e^{-2pi i n2 f1/256}
#pragma unroll
    for (int f1 = 0; f1 < 16; f1++) {
        float2 st = tw[(f1 << 4) & 255];
        float wr = 1.f, wi = 0.f, ar = 0.f, ai = 0.f;
#pragma unroll
        for (int n1 = 0; n1 < 16; n1++) {
            ar += xr[n1] * wr;
            ai += xr[n1] * wi;
            float nwr = wr * st.x - wi * st.y;
            wi = wr * st.y + wi * st.x;
            wr = nwr;
        }
        float2 t2 = tw[(t * f1) & 255];
        float pr = ar * t2.x - ai * t2.y;
        float pi = ar * t2.y + ai * t2.x;
        sbuf[g * 272 + t * 17 + f1] = make_float2(pr, pi);
    }
    __syncthreads();

    // Stage 2: X[f1+16f2] = sum_n2 A'[n2][f1] e^{-2pi i n2 f2/16}, only f<=128
    float2 a[16];
#pragma unroll
    for (int n2 = 0; n2 < 16; n2++) a[n2] = sbuf[g * 272 + n2 * 17 + t];
    __syncthreads(); // all reads done before sbuf is reused below

    int f1 = t;
    int f2max = (f1 == 0) ? 8 : 7;
    for (int f2 = 0; f2 <= f2max; f2++) {
        float2 st = tw[(f2 << 4) & 255];
        float wr = 1.f, wi = 0.f, Xr = 0.f, Xi = 0.f;
#pragma unroll
        for (int n2 = 0; n2 < 16; n2++) {
            Xr += a[n2].x * wr - a[n2].y * wi;
            Xi += a[n2].x * wi + a[n2].y * wr;
            float nwr = wr * st.x - wi * st.y;
            wi = wr * st.y + wi * st.x;
            wr = nwr;
        }
        sbuf[g * 129 + f1 + (f2 << 4)] = make_float2(Xr, Xi);
    }
    __syncthreads();

    // Coalesced write: X[b][f][j0..j0+15]
    for (int k = tid; k < 16 * 129; k += 256) {
        int jg = k & 15;
        int f  = k >> 4;
        g_X[((size_t)b * KH + f) * KIN + j0 + jg] = sbuf[jg * 129 + f];
    }
}

// ---------------------------------------------------------------------------
// Kernel 3: per-bin complex GEMM: Y[b][f][i] = sum_j X[b][f][j] * conj(W[f][i][j])
// CTA: one f, 128-row b tile. 64x64 W slice + 64x128 X tile in dynamic smem.
// ---------------------------------------------------------------------------
__global__ __launch_bounds__(256) void cgemm() {
    extern __shared__ float2 sm[];
    float2* sW = sm;          // [64 j][65] (padded)
    float2* sX = sm + 4160;   // [64 j][130] (padded)

    int f  = blockIdx.y;
    int b0 = blockIdx.x << 7;
    int tid = threadIdx.x;

    const float2* Wp = g_W + (size_t)f * 4096;
    for (int e = tid; e < 4096; e += 256) {
        int i = e >> 6, j = e & 63;
        sW[j * 65 + i] = Wp[e];
    }
    for (int e = tid; e < 8192; e += 256) {
        int bl = e >> 6, j = e & 63;
        sX[j * 130 + bl] = g_X[((size_t)(b0 + bl) * KH + f) * KIN + j];
    }
    __syncthreads();

    int ti = tid & 15;   // i = ti + 16*a
    int tb = tid >> 4;   // b = tb + 16*c
    float2 acc[4][8];
#pragma unroll
    for (int a2 = 0; a2 < 4; a2++)
#pragma unroll
        for (int c = 0; c < 8; c++) acc[a2][c] = make_float2(0.f, 0.f);

    for (int j = 0; j < 64; j++) {
        float2 wv[4];
        float2 xv[8];
#pragma unroll
        for (int a2 = 0; a2 < 4; a2++) wv[a2] = sW[j * 65 + ti + (a2 << 4)];
#pragma unroll
        for (int c = 0; c < 8; c++) xv[c] = sX[j * 130 + tb + (c << 4)];
#pragma unroll
        for (int a2 = 0; a2 < 4; a2++)
#pragma unroll
            for (int c = 0; c < 8; c++) {
                // acc += X * conj(W)
                acc[a2][c].x += xv[c].x * wv[a2].x + xv[c].y * wv[a2].y;
                acc[a2][c].y += xv[c].y * wv[a2].x - xv[c].x * wv[a2].y;
            }
    }

#pragma unroll
    for (int c = 0; c < 8; c++) {
        int b = b0 + tb + (c << 4);
        float2* yp = g_Y + ((size_t)b * KH + f) * KOUT;
#pragma unroll
        for (int a2 = 0; a2 < 4; a2++)
            yp[ti + (a2 << 4)] = acc[a2][c];
    }
}

// ---------------------------------------------------------------------------
// Kernel 4: inverse rFFT (reconstruct conj-symmetric spectrum from 129 bins),
// real output, scale 1/256. CTA: one b, 16 i-blocks.
// ---------------------------------------------------------------------------
__global__ __launch_bounds__(256) void fft_inv(float* __restrict__ out) {
    __shared__ float2 tw[256];
    __shared__ float2 sbuf[16 * 16 * 17]; // multi-use

    int tid = threadIdx.x;
    {
        float s, c;
        sincospif(-(float)tid * (1.0f / 128.0f), &s, &c);
        tw[tid] = make_float2(c, s); // e^{-2pi i k/256}; conj gives e^{+}
    }
    int cta = blockIdx.x;
    int b  = cta >> 2;
    int i0 = (cta & 3) << 4;
    int g  = tid >> 4;
    int t  = tid & 15;

    // Stage Y[b][0..128][i0..i0+15] into smem (coalesced), padded stride 17
    for (int k = tid; k < 129 * 16; k += 256) {
        int gg = k & 15;
        int f  = k >> 4;
        sbuf[f * 17 + gg] = g_Y[((size_t)b * KH + f) * KOUT + i0 + gg];
    }
    __syncthreads();

    // Gather Yfull[f1 + 16 f2] with conjugate symmetry
    int f1 = t;
    float2 y[16];
#pragma unroll
    for (int f2 = 0; f2 < 16; f2++) {
        int f = f1 + (f2 << 4);
        if (f <= 128) {
            y[f2] = sbuf[f * 17 + g];
        } else {
            float2 v = sbuf[(256 - f) * 17 + g];
            y[f2] = make_float2(v.x, -v.y);
        }
    }
    __syncthreads();

    // Stage 1: B'[f1][t1] = (sum_f2 y[f2] e^{+2pi i f2 t1/16}) * e^{+2pi i f1 t1/256}
#pragma unroll
    for (int t1 = 0; t1 < 16; t1++) {
        float2 stc = tw[(t1 << 4) & 255];
        float sr = stc.x, si = -stc.y; // conj -> e^{+}
        float wr = 1.f, wi = 0.f, br = 0.f, bi = 0.f;
#pragma unroll
        for (int f2 = 0; f2 < 16; f2++) {
            br += y[f2].x * wr - y[f2].y * wi;
            bi += y[f2].x * wi + y[f2].y * wr;
            float nwr = wr * sr - wi * si;
            wi = wr * si + wi * sr;
            wr = nwr;
        }
        float2 t2 = tw[(f1 * t1) & 255]; // use conj
        float pr =  br * t2.x + bi * t2.y;
        float pi = -br * t2.y + bi * t2.x;
        sbuf[g * 272 + f1 * 17 + t1] = make_float2(pr, pi);
    }
    __syncthreads();

    // Stage 2: out[t1+16t2] = Re( sum_f1 B'[f1][t1] e^{+2pi i f1 t2/16} ) / 256
    int t1 = t;
    float2 bb[16];
#pragma unroll
    for (int f1i = 0; f1i < 16; f1i++) bb[f1i] = sbuf[g * 272 + f1i * 17 + t1];
    __syncthreads();

    float* outs = (float*)sbuf; // 4096 floats
#pragma unroll
    for (int t2 = 0; t2 < 16; t2++) {
        float2 stc = tw[(t2 << 4) & 255];
        float sr = stc.x, si = -stc.y;
        float wr = 1.f, wi = 0.f, acc = 0.f;
#pragma unroll
        for (int f1i = 0; f1i < 16; f1i++) {
            acc += bb[f1i].x * wr - bb[f1i].y * wi;
            float nwr = wr * sr - wi * si;
            wi = wr * si + wi * sr;
            wr = nwr;
        }
        outs[g * 256 + t1 + (t2 << 4)] = acc * (1.0f / 256.0f);
    }
    __syncthreads();

    float* op = out + (size_t)b * 16384 + (size_t)i0 * 256;
    for (int k = tid; k < 4096; k += 256) op[k] = outs[k];
}

// ---------------------------------------------------------------------------
extern "C" void kernel_launch(void* const* d_in, const int* in_sizes, int n_in,
                              void* d_out, int out_size) {
    const float* x  = (const float*)d_in[0];
    const float* Wr = (const float*)d_in[1];
    const float* Wi = (const float*)d_in[2];
    float* out = (float*)d_out;

    cudaFuncSetAttribute(cgemm, cudaFuncAttributeMaxDynamicSharedMemorySize, 99840);

    prep_w<<<(KH * KOUT * KIN + 255) / 256, 256>>>(Wr, Wi);
    fft_fwd<<<B_SZ * (KIN / 16), 256>>>(x);
    cgemm<<<dim3(16, 129), 256, 99840>>>();
    fft_inv<<<B_SZ * (KOUT / 16), 256>>>(out);
}

// round 2
// speedup vs baseline: 1.8989x; 1.8989x over previous
#include <cuda_runtime.h>
#include <math.h>

#define B_SZ 2048
#define KIN  64
#define KOUT 64
#define BLK  256
#define KH   129

// Scratch (device globals: allocation-free per the rules)
__device__ float2 g_X[(size_t)B_SZ * KH * KIN];   // [b][f][j]  ~135 MB
__device__ float2 g_Y[(size_t)B_SZ * KH * KOUT];  // [b][f][i]  ~135 MB
__device__ float2 g_W[(size_t)KH * KOUT * KIN];   // [f][i][j]  ~4.2 MB

// ---------------------------------------------------------------------------
// Radix-2 DIF 16-point FFT, fully unrolled, constant twiddles.
// Natural-order input; output A[f] lives at a[REV4[f]].
// INV=false: e^{-2pi i}, INV=true: e^{+2pi i} (unnormalized).
// ---------------------------------------------------------------------------
#define FC1 0.9238795325112867f
#define FS1 0.3826834323650898f
#define FC2 0.7071067811865476f

// butterfly: (u,v) -> (u+v, (u-v)*(cr+i*ci)); cr/ci are literals -> folds
#define BF(i, j, cr, ci) {                                   \
    float ux = a[i].x, uy = a[i].y;                          \
    float vx = a[j].x, vy = a[j].y;                          \
    a[i].x = ux + vx; a[i].y = uy + vy;                      \
    float dx = ux - vx, dy = uy - vy;                        \
    a[j].x = dx * (cr) - dy * (ci);                          \
    a[j].y = dx * (ci) + dy * (cr); }

template<bool INV>
__device__ __forceinline__ void fft16_stages234(float2* a) {
    const float S = INV ? 1.0f : -1.0f;
    // stage 2: distance 4, twiddles W8^k
    BF(0, 4, 1.0f, 0.0f)   BF(1, 5, FC2, S * FC2)
    BF(2, 6, 0.0f, S)      BF(3, 7, -FC2, S * FC2)
    BF(8, 12, 1.0f, 0.0f)  BF(9, 13, FC2, S * FC2)
    BF(10, 14, 0.0f, S)    BF(11, 15, -FC2, S * FC2)
    // stage 3: distance 2, twiddles W4^k
    BF(0, 2, 1.0f, 0.0f)   BF(1, 3, 0.0f, S)
    BF(4, 6, 1.0f, 0.0f)   BF(5, 7, 0.0f, S)
    BF(8, 10, 1.0f, 0.0f)  BF(9, 11, 0.0f, S)
    BF(12, 14, 1.0f, 0.0f) BF(13, 15, 0.0f, S)
    // stage 4: distance 1
    BF(0, 1, 1.0f, 0.0f)   BF(2, 3, 1.0f, 0.0f)
    BF(4, 5, 1.0f, 0.0f)   BF(6, 7, 1.0f, 0.0f)
    BF(8, 9, 1.0f, 0.0f)   BF(10, 11, 1.0f, 0.0f)
    BF(12, 13, 1.0f, 0.0f) BF(14, 15, 1.0f, 0.0f)
}

template<bool INV>
__device__ __forceinline__ void fft16_full(float2* a) {
    const float S = INV ? 1.0f : -1.0f;
    // stage 1: distance 8, twiddles W16^k
    BF(0, 8, 1.0f, 0.0f)      BF(1, 9, FC1, S * FS1)
    BF(2, 10, FC2, S * FC2)   BF(3, 11, FS1, S * FC1)
    BF(4, 12, 0.0f, S)        BF(5, 13, -FS1, S * FC1)
    BF(6, 14, -FC2, S * FC2)  BF(7, 15, -FC1, S * FS1)
    fft16_stages234<INV>(a);
}

// real-input specialization of stage 1 (forward only)
__device__ __forceinline__ void fft16_real_fwd(const float* xr, float2* a) {
    const float tcr[8] = {1.0f, FC1, FC2, FS1, 0.0f, -FS1, -FC2, -FC1};
    const float tci[8] = {0.0f, -FS1, -FC2, -FC1, -1.0f, -FC1, -FC2, -FS1};
#pragma unroll
    for (int k = 0; k < 8; k++) {
        float s = xr[k] + xr[k + 8];
        float d = xr[k] - xr[k + 8];
        a[k]     = make_float2(s, 0.0f);
        a[k + 8] = make_float2(d * tcr[k], d * tci[k]);
    }
    fft16_stages234<false>(a);
}

// output position of frequency f after DIF (bit-reversal of 4 bits)
#define REV4_LIST {0, 8, 4, 12, 2, 10, 6, 14, 1, 9, 5, 13, 3, 11, 7, 15}

// ---------------------------------------------------------------------------
// Kernel 1: transpose W (i,j,f) -> (f,i,j) as complex
// ---------------------------------------------------------------------------
__global__ void prep_w(const float* __restrict__ Wr, const float* __restrict__ Wi) {
    int idx = blockIdx.x * blockDim.x + threadIdx.x;
    if (idx >= KH * KOUT * KIN) return;
    int j = idx & 63;
    int i = (idx >> 6) & 63;
    int f = idx >> 12;
    float2 v;
    v.x = Wr[(i * KIN + j) * KH + f];
    v.y = Wi[(i * KIN + j) * KH + f];
    g_W[idx] = v;
}

// ---------------------------------------------------------------------------
// Kernel 2: forward rFFT (256-pt, 16x16 Cooley-Tukey, radix-2 butterflies)
// CTA: one b, 16 j-blocks. Writes X[b][f][j], f = 0..128 only.
// ---------------------------------------------------------------------------
__global__ __launch_bounds__(256) void fft_fwd(const float* __restrict__ x) {
    __shared__ float2 tw[256];            // tw[k] = e^{-2pi i k/256}
    __shared__ float2 sbuf[16 * 16 * 17]; // multi-use

    const int rev[16] = REV4_LIST;
    int tid = threadIdx.x;
    {
        float s, c;
        sincospif(-(float)tid * (1.0f / 128.0f), &s, &c);
        tw[tid] = make_float2(c, s);
    }
    int cta = blockIdx.x;
    int b  = cta >> 2;
    int j0 = (cta & 3) << 4;
    int g  = tid >> 4;   // FFT index within CTA (j = j0+g)
    int t  = tid & 15;   // lane within FFT: n2 in stage 1, f1 in stage 2

    // Load x[16*n1 + t] for this block
    const float* xp = x + (size_t)b * 16384 + (size_t)(j0 + g) * 256 + t;
    float xr[16];
#pragma unroll
    for (int n1 = 0; n1 < 16; n1++) xr[n1] = xp[n1 * 16];

    __syncthreads(); // twiddle table ready

    // Stage 1: 16-pt real FFT over n1, then inter-stage twiddle e^{-2pi i n2 f1/256}
    float2 a[16];
    fft16_real_fwd(xr, a);
#pragma unroll
    for (int f1 = 0; f1 < 16; f1++) {
        float2 A = a[rev[f1]];
        float2 t2 = tw[(t * f1) & 255];
        float pr = A.x * t2.x - A.y * t2.y;
        float pi = A.x * t2.y + A.y * t2.x;
        sbuf[g * 272 + t * 17 + f1] = make_float2(pr, pi);
    }
    __syncthreads();

    // Stage 2: 16-pt complex FFT over n2, keep f = f1 + 16 f2 <= 128
    float2 c[16];
#pragma unroll
    for (int n2 = 0; n2 < 16; n2++) c[n2] = sbuf[g * 272 + n2 * 17 + t];
    __syncthreads(); // all reads done before sbuf reuse

    {
        float2* a2 = c;
        {
            float2* a = a2;
            fft16_full<false>(a);
        }
        int f1 = t;
#pragma unroll
        for (int f2 = 0; f2 < 16; f2++) {
            int f = f1 + (f2 << 4);
            if (f <= 128) sbuf[g * 129 + f] = c[rev[f2]];
        }
    }
    __syncthreads();

    // Coalesced write: X[b][f][j0..j0+15]
    for (int k = tid; k < 16 * 129; k += 256) {
        int jg = k & 15;
        int f  = k >> 4;
        g_X[((size_t)b * KH + f) * KIN + j0 + jg] = sbuf[jg * 129 + f];
    }
}

// ---------------------------------------------------------------------------
// Kernel 3: per-bin complex GEMM: Y[b][f][i] = sum_j X[b][f][j] * conj(W[f][i][j])
// CTA: one f, 128-row b tile. 64x64 W slice + 64x128 X tile in dynamic smem.
// ---------------------------------------------------------------------------
__global__ __launch_bounds__(256) void cgemm() {
    extern __shared__ float2 sm[];
    float2* sW = sm;          // [64 j][65] (padded)
    float2* sX = sm + 4160;   // [64 j][130] (padded)

    int f  = blockIdx.y;
    int b0 = blockIdx.x << 7;
    int tid = threadIdx.x;

    const float2* Wp = g_W + (size_t)f * 4096;
    for (int e = tid; e < 4096; e += 256) {
        int i = e >> 6, j = e & 63;
        sW[j * 65 + i] = Wp[e];
    }
    for (int e = tid; e < 8192; e += 256) {
        int bl = e >> 6, j = e & 63;
        sX[j * 130 + bl] = g_X[((size_t)(b0 + bl) * KH + f) * KIN + j];
    }
    __syncthreads();

    int ti = tid & 15;   // i = ti + 16*a
    int tb = tid >> 4;   // b = tb + 16*c
    float2 acc[4][8];
#pragma unroll
    for (int a2 = 0; a2 < 4; a2++)
#pragma unroll
        for (int c = 0; c < 8; c++) acc[a2][c] = make_float2(0.f, 0.f);

    for (int j = 0; j < 64; j++) {
        float2 wv[4];
        float2 xv[8];
#pragma unroll
        for (int a2 = 0; a2 < 4; a2++) wv[a2] = sW[j * 65 + ti + (a2 << 4)];
#pragma unroll
        for (int c = 0; c < 8; c++) xv[c] = sX[j * 130 + tb + (c << 4)];
#pragma unroll
        for (int a2 = 0; a2 < 4; a2++)
#pragma unroll
            for (int c = 0; c < 8; c++) {
                // acc += X * conj(W)
                acc[a2][c].x += xv[c].x * wv[a2].x + xv[c].y * wv[a2].y;
                acc[a2][c].y += xv[c].y * wv[a2].x - xv[c].x * wv[a2].y;
            }
    }

#pragma unroll
    for (int c = 0; c < 8; c++) {
        int b = b0 + tb + (c << 4);
        float2* yp = g_Y + ((size_t)b * KH + f) * KOUT;
#pragma unroll
        for (int a2 = 0; a2 < 4; a2++)
            yp[ti + (a2 << 4)] = acc[a2][c];
    }
}

// ---------------------------------------------------------------------------
// Kernel 4: inverse rFFT (radix-2 butterflies), real output, scale 1/256.
// CTA: one b, 16 i-blocks.
// ---------------------------------------------------------------------------
__global__ __launch_bounds__(256) void fft_inv(float* __restrict__ out) {
    __shared__ float2 tw[256];
    __shared__ float2 sbuf[16 * 16 * 17]; // multi-use

    const int rev[16] = REV4_LIST;
    int tid = threadIdx.x;
    {
        float s, c;
        sincospif(-(float)tid * (1.0f / 128.0f), &s, &c);
        tw[tid] = make_float2(c, s); // e^{-2pi i k/256}; conj gives e^{+}
    }
    int cta = blockIdx.x;
    int b  = cta >> 2;
    int i0 = (cta & 3) << 4;
    int g  = tid >> 4;
    int t  = tid & 15;

    // Stage Y[b][0..128][i0..i0+15] into smem (coalesced), padded stride 17
    for (int k = tid; k < 129 * 16; k += 256) {
        int gg = k & 15;
        int f  = k >> 4;
        sbuf[f * 17 + gg] = g_Y[((size_t)b * KH + f) * KOUT + i0 + gg];
    }
    __syncthreads();

    // Gather Yfull[f1 + 16 f2] with conjugate symmetry
    int f1 = t;
    float2 a[16];
#pragma unroll
    for (int f2 = 0; f2 < 16; f2++) {
        int f = f1 + (f2 << 4);
        if (f <= 128) {
            a[f2] = sbuf[f * 17 + g];
        } else {
            float2 v = sbuf[(256 - f) * 17 + g];
            a[f2] = make_float2(v.x, -v.y);
        }
    }
    __syncthreads();

    // Stage 1: inverse 16-pt FFT over f2, then conj inter-stage twiddle
    fft16_full<true>(a);
#pragma unroll
    for (int t1 = 0; t1 < 16; t1++) {
        float2 B = a[rev[t1]];
        float2 t2 = tw[(f1 * t1) & 255]; // conj applied below
        float pr =  B.x * t2.x + B.y * t2.y;
        float pi = -B.x * t2.y + B.y * t2.x;
        sbuf[g * 272 + f1 * 17 + t1] = make_float2(pr, pi);
    }
    __syncthreads();

    // Stage 2: inverse 16-pt FFT over f1, real part, scale 1/256
    int t1 = t;
    float2 bb[16];
#pragma unroll
    for (int f1i = 0; f1i < 16; f1i++) bb[f1i] = sbuf[g * 272 + f1i * 17 + t1];
    __syncthreads();

    fft16_full<true>(bb);

    float* outs = (float*)sbuf; // 4096 floats
#pragma unroll
    for (int t2 = 0; t2 < 16; t2++) {
        outs[g * 256 + t1 + (t2 << 4)] = bb[rev[t2]].x * (1.0f / 256.0f);
    }
    __syncthreads();

    float* op = out + (size_t)b * 16384 + (size_t)i0 * 256;
    for (int k = tid; k < 4096; k += 256) op[k] = outs[k];
}

// ---------------------------------------------------------------------------
extern "C" void kernel_launch(void* const* d_in, const int* in_sizes, int n_in,
                              void* d_out, int out_size) {
    const float* x  = (const float*)d_in[0];
    const float* Wr = (const float*)d_in[1];
    const float* Wi = (const float*)d_in[2];
    float* out = (float*)d_out;

    cudaFuncSetAttribute(cgemm, cudaFuncAttributeMaxDynamicSharedMemorySize, 99840);

    prep_w<<<(KH * KOUT * KIN + 255) / 256, 256>>>(Wr, Wi);
    fft_fwd<<<B_SZ * (KIN / 16), 256>>>(x);
    cgemm<<<dim3(16, 129), 256, 99840>>>();
    fft_inv<<<B_SZ * (KOUT / 16), 256>>>(out);
}